// round 12
// baseline (speedup 1.0000x reference)
#include <cuda_runtime.h>
#include <cuda_bf16.h>
#include <cstdint>
#include <cstddef>

// ---------------- problem constants ----------------
constexpr int kC  = 1024;
constexpr int kE  = 8;
constexpr int kH  = 4096;
constexpr int kN  = 8192;
constexpr int kBM = 128;               // CTA M tile
constexpr int kBN = 128;               // CTA N tile
constexpr int kRMax = kN + kE * kBM;   // 9216 padded rows
constexpr int kNRT  = kRMax / kBM;     // 72 row tiles
constexpr int kRegB  = kBM * 48;       // 6144 B per region (128 rows x 48B stride)
constexpr int kStageB = 4 * kRegB;     // Ahi|Alo|Bhi|Blo = 24576 B
constexpr int kDynSmem = 2 * kStageB;  // 49152 B = 48KB per CTA

// ---------------- device scratch (189MB profile, proven safe) ----------------
// g_xg / g_h hold hi-plane then lo-plane of packed bf16 pairs (2 per u32).
__device__ uint32_t g_xg[(size_t)kRMax * kC];
__device__ uint32_t g_h [(size_t)kRMax * kH];
__device__ float g_prob[kN];
__device__ int   g_idx[kN];
__device__ int   g_perm[kRMax];
__device__ int   g_cnt[kE];
__device__ int   g_cur[kE];
__device__ int   g_poff[kE + 1];

constexpr size_t kXPlane = (size_t)kRMax * (kC / 2);   // u32 per plane
constexpr size_t kHPlane = (size_t)kRMax * (kH / 2);

// ---------------- helpers ----------------
__device__ __forceinline__ uint32_t smem_u32(const void* p) {
    uint32_t a;
    asm("{ .reg .u64 t; cvta.to.shared.u64 t, %1; cvt.u32.u64 %0, t; }" : "=r"(a) : "l"(p));
    return a;
}

#define LDSM4(r, a) \
    asm volatile("ldmatrix.sync.aligned.m8n8.x4.shared.b16 {%0,%1,%2,%3}, [%4];" \
                 : "=r"((r)[0]), "=r"((r)[1]), "=r"((r)[2]), "=r"((r)[3]) : "r"(a))

__device__ __forceinline__ void mma16816(float* c, const uint32_t* a, const uint32_t* b) {
    asm volatile(
        "mma.sync.aligned.m16n8k16.row.col.f32.bf16.bf16.f32 "
        "{%0,%1,%2,%3}, {%4,%5,%6,%7}, {%8,%9}, {%0,%1,%2,%3};\n"
        : "+f"(c[0]), "+f"(c[1]), "+f"(c[2]), "+f"(c[3])
        : "r"(a[0]), "r"(a[1]), "r"(a[2]), "r"(a[3]), "r"(b[0]), "r"(b[1]));
}

__device__ __forceinline__ float geluf(float v) {
    return 0.5f * v * (1.0f + erff(v * 0.70710678118654752f));
}
// pack {v1,v0} -> bf16x2 (v0 in low half), RN rounding
__device__ __forceinline__ uint32_t cvt_bf16x2(float v0, float v1) {
    uint32_t r;
    asm("cvt.rn.bf16x2.f32 %0, %1, %2;" : "=r"(r) : "f"(v1), "f"(v0));
    return r;
}
__device__ __forceinline__ void split_pack(float v0, float v1, uint32_t& hp, uint32_t& lp) {
    hp = cvt_bf16x2(v0, v1);
    float h0 = __uint_as_float(hp << 16);
    float h1 = __uint_as_float(hp & 0xFFFF0000u);
    lp = cvt_bf16x2(v0 - h0, v1 - h1);
}

// ---------------- small kernels ----------------
__global__ void reset_kernel() {
    int t = threadIdx.x;
    if (t < kE) { g_cnt[t] = 0; g_cur[t] = 0; }
}

__global__ void router_kernel(const float* __restrict__ x,
                              const float* __restrict__ Wr,
                              const float* __restrict__ br) {
    int tok  = (blockIdx.x * blockDim.x + threadIdx.x) >> 5;
    int lane = threadIdx.x & 31;
    if (tok >= kN) return;
    const float* xr = x + (size_t)tok * kC;
    float acc[kE];
#pragma unroll
    for (int e = 0; e < kE; e++) acc[e] = 0.f;
    for (int c = lane; c < kC; c += 32) {
        float xv = xr[c];
        const float4* w = (const float4*)(Wr + (size_t)c * kE);
        float4 w0 = w[0], w1 = w[1];
        acc[0] += xv * w0.x; acc[1] += xv * w0.y; acc[2] += xv * w0.z; acc[3] += xv * w0.w;
        acc[4] += xv * w1.x; acc[5] += xv * w1.y; acc[6] += xv * w1.z; acc[7] += xv * w1.w;
    }
#pragma unroll
    for (int e = 0; e < kE; e++)
        for (int o = 16; o > 0; o >>= 1)
            acc[e] += __shfl_xor_sync(0xffffffffu, acc[e], o);
    if (lane == 0) {
        float m = -1e30f; int bi = 0;
#pragma unroll
        for (int e = 0; e < kE; e++) {
            acc[e] += br[e];
            if (acc[e] > m) { m = acc[e]; bi = e; }
        }
        float s = 0.f;
#pragma unroll
        for (int e = 0; e < kE; e++) s += expf(acc[e] - m);
        g_prob[tok] = 1.f / s;
        g_idx[tok]  = bi;
        atomicAdd(&g_cnt[bi], 1);
    }
}

__global__ void offsets_kernel(float* aux_out) {
    if (threadIdx.x == 0) {
        int p = 0; float s = 0.f;
#pragma unroll
        for (int e = 0; e < kE; e++) {
            g_poff[e] = p;
            int c = g_cnt[e];
            p += (c + kBM - 1) / kBM * kBM;
            float f = (float)c / (float)kN;
            float d = f - (1.0f / (float)kE);
            s += d * d;
        }
        g_poff[kE] = p;
        if (aux_out) *aux_out = s / (float)kE;
    }
}

// gather: x -> hi/lo planes of packed bf16 pairs
__global__ void gather_kernel(const float* __restrict__ x) {
    int tok  = (blockIdx.x * blockDim.x + threadIdx.x) >> 5;
    int lane = threadIdx.x & 31;
    if (tok >= kN) return;
    int e = g_idx[tok];
    int pos = 0;
    if (lane == 0) pos = g_poff[e] + atomicAdd(&g_cur[e], 1);
    pos = __shfl_sync(0xffffffffu, pos, 0);
    if (lane == 0) g_perm[pos] = tok;
    const float2* src = (const float2*)(x + (size_t)tok * kC);
    uint32_t* dh = g_xg + (size_t)pos * (kC / 2);
    uint32_t* dl = dh + kXPlane;
#pragma unroll
    for (int g = 0; g < 16; g++) {
        float2 v = src[g * 32 + lane];
        uint32_t hp, lp;
        split_pack(v.x, v.y, hp, lp);
        dh[g * 32 + lane] = hp;
        dl[g * 32 + lane] = lp;
    }
}

// ---------------- grouped GEMM: 256 threads, 2 CTAs/SM ----------------
// SECOND=false: g_h(planes) = gelu(xg @ W1[e] + b1)
// SECOND=true : out[perm[r]] = prob * (h @ W2[e] + b2)
template <bool SECOND>
__global__ __launch_bounds__(256, 2)
void moe_mma(const float* __restrict__ Wsrc, const float* __restrict__ bias,
             float* __restrict__ OutP) {
    constexpr int KDIM = SECOND ? kH : kC;
    constexpr int ND   = SECOND ? kC : kH;
    constexpr int KB   = KDIM / 16;
    constexpr int KW   = KDIM / 2;                 // u32 per row in a plane

    extern __shared__ char smc[];
    const uint32_t sb = smem_u32(smc);

    const int rt = blockIdx.y, bx = blockIdx.x;
    const int row0 = rt * kBM;
    if (row0 >= g_poff[kE]) return;
    int e = 0;
    while (e < kE - 1 && row0 >= g_poff[e + 1]) e++;

    const uint32_t* Ahi = (SECOND ? g_h : g_xg) + (size_t)row0 * KW;
    const uint32_t* Alo = Ahi + (SECOND ? kHPlane : kXPlane);
    const float*    B   = Wsrc + (size_t)e * KDIM * ND + (size_t)bx * kBN;

    const int tid  = threadIdx.x;
    const int warp = tid >> 5;
    const int lane = tid & 31;
    const int wm   = warp & 3;
    const int wn   = warp >> 2;

    // A fill: thread -> (row, 16B half), pre-split planes
    const int arow = tid >> 1, ah = tid & 1;
    const uint32_t* AhiP = Ahi + (size_t)arow * KW + ah * 4;
    const uint32_t* AloP = Alo + (size_t)arow * KW + ah * 4;
    char* const adst = smc + (size_t)arow * 48 + (size_t)ah * 16;

    // B fill: thread -> (n col, k octet)
    const int bn = tid & 127, bkp = tid >> 7;
    const float* Bload = B + (size_t)bkp * 8 * ND + bn;
    char* const bdst = smc + 2 * kRegB + (size_t)bn * 48 + (size_t)bkp * 16;

    uint4 rh4, rl4;
    float rb[8];
    auto loadBlk = [&](int kb) {
        rh4 = *(const uint4*)(AhiP + kb * 8);
        rl4 = *(const uint4*)(AloP + kb * 8);
#pragma unroll
        for (int i = 0; i < 8; i++)
            rb[i] = Bload[(size_t)(kb * 16 + i) * ND];
    };
    auto storeBlk = [&](int s) {
        *(uint4*)(adst + (size_t)s * kStageB)         = rh4;
        *(uint4*)(adst + (size_t)s * kStageB + kRegB) = rl4;
        uint32_t hp[4], lp[4];
#pragma unroll
        for (int i = 0; i < 4; i++)
            split_pack(rb[2 * i], rb[2 * i + 1], hp[i], lp[i]);
        char* base = bdst + (size_t)s * kStageB;
        *(uint4*)(base)         = make_uint4(hp[0], hp[1], hp[2], hp[3]);
        *(uint4*)(base + kRegB) = make_uint4(lp[0], lp[1], lp[2], lp[3]);
    };

    // ldmatrix byte offsets within one region (row stride 48B)
    uint32_t offA[2], offB[4];
#pragma unroll
    for (int i = 0; i < 2; i++) {
        uint32_t row = wm * 32 + i * 16 + ((lane >> 3) & 1) * 8 + (lane & 7);
        offA[i] = row * 48 + (lane >> 4) * 16;
    }
#pragma unroll
    for (int jp = 0; jp < 4; jp++) {
        uint32_t row = wn * 64 + jp * 16 + (lane >> 4) * 8 + (lane & 7);
        offB[jp] = row * 48 + ((lane >> 3) & 1) * 16;
    }

    float acc[2][8][4];
#pragma unroll
    for (int i = 0; i < 2; i++)
#pragma unroll
        for (int j = 0; j < 8; j++)
#pragma unroll
            for (int q = 0; q < 4; q++) acc[i][j][q] = 0.f;

    loadBlk(0);
    storeBlk(0);
    __syncthreads();

    for (int kb = 0; kb < KB; kb++) {
        const int s = kb & 1;
        const uint32_t st = sb + (uint32_t)s * kStageB;

        uint32_t ahi[2][4], alo[2][4], bhi[4][4], blo[4][4];
#pragma unroll
        for (int i = 0; i < 2; i++) {
            LDSM4(ahi[i], st + offA[i]);
            LDSM4(alo[i], st + (uint32_t)kRegB + offA[i]);
        }
#pragma unroll
        for (int jp = 0; jp < 4; jp++) {
            LDSM4(bhi[jp], st + 2u * kRegB + offB[jp]);
            LDSM4(blo[jp], st + 3u * kRegB + offB[jp]);
        }

        if (kb + 1 < KB) loadBlk(kb + 1);   // LDG for next block; covered by MMA below

#pragma unroll
        for (int i = 0; i < 2; i++)
#pragma unroll
            for (int j = 0; j < 8; j++) {
                int jp = j >> 1, s2 = (j & 1) * 2;
                mma16816(acc[i][j], ahi[i], &bhi[jp][s2]);
                mma16816(acc[i][j], ahi[i], &blo[jp][s2]);
                mma16816(acc[i][j], alo[i], &bhi[jp][s2]);
            }

        if (kb + 1 < KB) storeBlk(s ^ 1);
        __syncthreads();
    }

    // ---------------- epilogue ----------------
    const int realEnd = g_poff[e] + g_cnt[e];
    const float* biasE = bias + (size_t)e * ND + (size_t)bx * kBN;
    const int r0 = wm * 32 + (lane >> 2);
    const int c0 = (lane & 3) * 2;

#pragma unroll
    for (int i = 0; i < 2; i++)
#pragma unroll
        for (int hh = 0; hh < 2; hh++) {
            int r = row0 + r0 + i * 16 + hh * 8;
            if (r >= realEnd) continue;
            if (!SECOND) {
                uint32_t* hrh = g_h + (size_t)r * (kH / 2) + (size_t)bx * (kBN / 2);
                uint32_t* hrl = hrh + kHPlane;
#pragma unroll
                for (int j = 0; j < 8; j++) {
                    int col = wn * 64 + j * 8 + c0;
                    float v0 = geluf(acc[i][j][hh * 2 + 0] + biasE[col]);
                    float v1 = geluf(acc[i][j][hh * 2 + 1] + biasE[col + 1]);
                    uint32_t hp, lp;
                    split_pack(v0, v1, hp, lp);
                    hrh[col >> 1] = hp;
                    hrl[col >> 1] = lp;
                }
            } else {
                int n = g_perm[r];
                float sc = g_prob[n];
                float* orow = OutP + (size_t)n * kC + (size_t)bx * kBN;
#pragma unroll
                for (int j = 0; j < 8; j++) {
                    int col = wn * 64 + j * 8 + c0;
                    float2 v;
                    v.x = (acc[i][j][hh * 2 + 0] + biasE[col]) * sc;
                    v.y = (acc[i][j][hh * 2 + 1] + biasE[col + 1]) * sc;
                    *(float2*)(orow + col) = v;
                }
            }
        }
}

// ---------------- launch ----------------
extern "C" void kernel_launch(void* const* d_in, const int* in_sizes, int n_in,
                              void* d_out, int out_size) {
    const float* x  = (const float*)d_in[0];
    const float* Wr = (const float*)d_in[1];
    const float* br = (const float*)d_in[2];
    const float* W1 = (const float*)d_in[3];
    const float* b1 = (const float*)d_in[4];
    const float* W2 = (const float*)d_in[5];
    const float* b2 = (const float*)d_in[6];
    float* out = (float*)d_out;
    (void)n_in;

    reset_kernel<<<1, 32>>>();
    router_kernel<<<kN / 8, 256>>>(x, Wr, br);
    float* auxp = (out_size > kN * kC) ? out + (size_t)kN * kC : nullptr;
    offsets_kernel<<<1, 1>>>(auxp);
    gather_kernel<<<kN / 8, 256>>>(x);

    moe_mma<false><<<dim3(kH / kBN, kNRT), 256, kDynSmem>>>(W1, b1, nullptr);
    moe_mma<true ><<<dim3(kC / kBN, kNRT), 256, kDynSmem>>>(W2, b2, out);
}

// round 14
// speedup vs baseline: 1.4077x; 1.4077x over previous
#include <cuda_runtime.h>
#include <cuda_bf16.h>
#include <cstdint>
#include <cstddef>

// ---------------- problem constants ----------------
constexpr int kC  = 1024;
constexpr int kE  = 8;
constexpr int kH  = 4096;
constexpr int kN  = 8192;
constexpr int kBM = 128;               // CTA M tile
constexpr int kBN = 128;               // CTA N tile
constexpr int kRMax = kN + kE * kBM;   // 9216 padded rows
constexpr int kNRT  = kRMax / kBM;     // 72 row tiles
constexpr int kRegB  = kBM * 32;       // 4096 B per region (128 rows x 32B tight stride)
constexpr int kStageB = 4 * kRegB;     // Ahi|Alo|Bhi|Blo = 16384 B
constexpr int kDynSmem = 3 * kStageB;  // 49152 B = 48KB (3 stages, no opt-in)

// ---------------- device scratch (189MB profile, proven safe) ----------------
// g_xg / g_h hold hi-plane then lo-plane of packed bf16 pairs (2 per u32).
__device__ uint32_t g_xg[(size_t)kRMax * kC];
__device__ uint32_t g_h [(size_t)kRMax * kH];
__device__ float g_prob[kN];
__device__ int   g_idx[kN];
__device__ int   g_perm[kRMax];
__device__ int   g_cnt[kE];
__device__ int   g_cur[kE];
__device__ int   g_poff[kE + 1];

constexpr size_t kXPlane = (size_t)kRMax * (kC / 2);   // u32 per plane
constexpr size_t kHPlane = (size_t)kRMax * (kH / 2);

// ---------------- helpers ----------------
__device__ __forceinline__ uint32_t smem_u32(const void* p) {
    uint32_t a;
    asm("{ .reg .u64 t; cvta.to.shared.u64 t, %1; cvt.u32.u64 %0, t; }" : "=r"(a) : "l"(p));
    return a;
}

#define LDSM4(r, a) \
    asm volatile("ldmatrix.sync.aligned.m8n8.x4.shared.b16 {%0,%1,%2,%3}, [%4];" \
                 : "=r"((r)[0]), "=r"((r)[1]), "=r"((r)[2]), "=r"((r)[3]) : "r"(a))

__device__ __forceinline__ void mma16816(float* c, const uint32_t* a, const uint32_t* b) {
    asm volatile(
        "mma.sync.aligned.m16n8k16.row.col.f32.bf16.bf16.f32 "
        "{%0,%1,%2,%3}, {%4,%5,%6,%7}, {%8,%9}, {%0,%1,%2,%3};\n"
        : "+f"(c[0]), "+f"(c[1]), "+f"(c[2]), "+f"(c[3])
        : "r"(a[0]), "r"(a[1]), "r"(a[2]), "r"(a[3]), "r"(b[0]), "r"(b[1]));
}

__device__ __forceinline__ float geluf(float v) {
    return 0.5f * v * (1.0f + erff(v * 0.70710678118654752f));
}
// pack {v1,v0} -> bf16x2 (v0 in low half), RN rounding
__device__ __forceinline__ uint32_t cvt_bf16x2(float v0, float v1) {
    uint32_t r;
    asm("cvt.rn.bf16x2.f32 %0, %1, %2;" : "=r"(r) : "f"(v1), "f"(v0));
    return r;
}
__device__ __forceinline__ void split_pack(float v0, float v1, uint32_t& hp, uint32_t& lp) {
    hp = cvt_bf16x2(v0, v1);
    float h0 = __uint_as_float(hp << 16);
    float h1 = __uint_as_float(hp & 0xFFFF0000u);
    lp = cvt_bf16x2(v0 - h0, v1 - h1);
}

// ---------------- small kernels ----------------
__global__ void reset_kernel() {
    int t = threadIdx.x;
    if (t < kE) { g_cnt[t] = 0; g_cur[t] = 0; }
}

__global__ void router_kernel(const float* __restrict__ x,
                              const float* __restrict__ Wr,
                              const float* __restrict__ br) {
    int tok  = (blockIdx.x * blockDim.x + threadIdx.x) >> 5;
    int lane = threadIdx.x & 31;
    if (tok >= kN) return;
    const float* xr = x + (size_t)tok * kC;
    float acc[kE];
#pragma unroll
    for (int e = 0; e < kE; e++) acc[e] = 0.f;
    for (int c = lane; c < kC; c += 32) {
        float xv = xr[c];
        const float4* w = (const float4*)(Wr + (size_t)c * kE);
        float4 w0 = w[0], w1 = w[1];
        acc[0] += xv * w0.x; acc[1] += xv * w0.y; acc[2] += xv * w0.z; acc[3] += xv * w0.w;
        acc[4] += xv * w1.x; acc[5] += xv * w1.y; acc[6] += xv * w1.z; acc[7] += xv * w1.w;
    }
#pragma unroll
    for (int e = 0; e < kE; e++)
        for (int o = 16; o > 0; o >>= 1)
            acc[e] += __shfl_xor_sync(0xffffffffu, acc[e], o);
    if (lane == 0) {
        float m = -1e30f; int bi = 0;
#pragma unroll
        for (int e = 0; e < kE; e++) {
            acc[e] += br[e];
            if (acc[e] > m) { m = acc[e]; bi = e; }
        }
        float s = 0.f;
#pragma unroll
        for (int e = 0; e < kE; e++) s += expf(acc[e] - m);
        g_prob[tok] = 1.f / s;
        g_idx[tok]  = bi;
        atomicAdd(&g_cnt[bi], 1);
    }
}

__global__ void offsets_kernel(float* aux_out) {
    if (threadIdx.x == 0) {
        int p = 0; float s = 0.f;
#pragma unroll
        for (int e = 0; e < kE; e++) {
            g_poff[e] = p;
            int c = g_cnt[e];
            p += (c + kBM - 1) / kBM * kBM;
            float f = (float)c / (float)kN;
            float d = f - (1.0f / (float)kE);
            s += d * d;
        }
        g_poff[kE] = p;
        if (aux_out) *aux_out = s / (float)kE;
    }
}

// gather: x -> hi/lo planes of packed bf16 pairs
__global__ void gather_kernel(const float* __restrict__ x) {
    int tok  = (blockIdx.x * blockDim.x + threadIdx.x) >> 5;
    int lane = threadIdx.x & 31;
    if (tok >= kN) return;
    int e = g_idx[tok];
    int pos = 0;
    if (lane == 0) pos = g_poff[e] + atomicAdd(&g_cur[e], 1);
    pos = __shfl_sync(0xffffffffu, pos, 0);
    if (lane == 0) g_perm[pos] = tok;
    const float2* src = (const float2*)(x + (size_t)tok * kC);
    uint32_t* dh = g_xg + (size_t)pos * (kC / 2);
    uint32_t* dl = dh + kXPlane;
#pragma unroll
    for (int g = 0; g < 16; g++) {
        float2 v = src[g * 32 + lane];
        uint32_t hp, lp;
        split_pack(v.x, v.y, hp, lp);
        dh[g * 32 + lane] = hp;
        dl[g * 32 + lane] = lp;
    }
}

// ---------------- grouped GEMM: 3-stage ring, fragment prefetch -------------
// SECOND=false: g_h(planes) = gelu(xg @ W1[e] + b1)
// SECOND=true : out[perm[r]] = prob * (h @ W2[e] + b2)
struct Frags {
    uint32_t ahi[2][4], alo[2][4], bhi[4][4], blo[4][4];
};

template <bool SECOND>
__global__ __launch_bounds__(256)
void moe_mma(const float* __restrict__ Wsrc, const float* __restrict__ bias,
             float* __restrict__ OutP) {
    constexpr int KDIM = SECOND ? kH : kC;
    constexpr int ND   = SECOND ? kC : kH;
    constexpr int KB   = KDIM / 16;            // even (64 / 256)
    constexpr int KW   = KDIM / 2;             // u32 per row in a plane

    extern __shared__ char smc[];
    const uint32_t sb = smem_u32(smc);

    const int rt = blockIdx.y, bx = blockIdx.x;
    const int row0 = rt * kBM;
    if (row0 >= g_poff[kE]) return;
    int e = 0;
    while (e < kE - 1 && row0 >= g_poff[e + 1]) e++;

    const uint32_t* Ahi = (SECOND ? g_h : g_xg) + (size_t)row0 * KW;
    const uint32_t* Alo = Ahi + (SECOND ? kHPlane : kXPlane);
    const float*    B   = Wsrc + (size_t)e * KDIM * ND + (size_t)bx * kBN;

    const int tid  = threadIdx.x;
    const int warp = tid >> 5;
    const int lane = tid & 31;
    const int wm   = warp & 3;
    const int wn   = warp >> 2;

    // A fill: thread -> (row = tid>>1, 16B half = tid&1); STS addr = tid*16 (linear)
    const int arow = tid >> 1, ah = tid & 1;
    const uint32_t* AhiP = Ahi + (size_t)arow * KW + ah * 4;
    const uint32_t* AloP = Alo + (size_t)arow * KW + ah * 4;

    // B fill: thread -> (n col = tid>>1, k octet = tid&1); STS addr = tid*16 (linear)
    const int bn = tid >> 1, bkp = tid & 1;
    const float* Bload = B + (size_t)bkp * 8 * ND + bn;

    uint4 rh4, rl4;
    float rb[8];
    auto loadBlk = [&](int kb) {
        rh4 = *(const uint4*)(AhiP + kb * 8);
        rl4 = *(const uint4*)(AloP + kb * 8);
#pragma unroll
        for (int i = 0; i < 8; i++)
            rb[i] = Bload[(size_t)(kb * 16 + i) * ND];
    };
    auto storeBlk = [&](int stageOff) {
        char* base = smc + stageOff + (size_t)tid * 16;
        *(uint4*)(base)         = rh4;
        *(uint4*)(base + kRegB) = rl4;
        uint32_t hp[4], lp[4];
#pragma unroll
        for (int i = 0; i < 4; i++)
            split_pack(rb[2 * i], rb[2 * i + 1], hp[i], lp[i]);
        *(uint4*)(base + 2 * kRegB) = make_uint4(hp[0], hp[1], hp[2], hp[3]);
        *(uint4*)(base + 3 * kRegB) = make_uint4(lp[0], lp[1], lp[2], lp[3]);
    };

    // ldmatrix byte offsets within one region (tight 32B row stride; each
    // LDSM.x4 reads a contiguous 512B-aligned window -> conflict-free)
    uint32_t offA[2], offB[4];
#pragma unroll
    for (int i = 0; i < 2; i++) {
        uint32_t row = wm * 32 + i * 16 + ((lane >> 3) & 1) * 8 + (lane & 7);
        offA[i] = row * 32 + (lane >> 4) * 16;
    }
#pragma unroll
    for (int jp = 0; jp < 4; jp++) {
        uint32_t row = wn * 64 + jp * 16 + (lane >> 4) * 8 + (lane & 7);
        offB[jp] = row * 32 + ((lane >> 3) & 1) * 16;
    }

    auto ldsmFrags = [&](Frags& f, uint32_t stageOff) {
        const uint32_t st = sb + stageOff;
#pragma unroll
        for (int i = 0; i < 2; i++) {
            LDSM4(f.ahi[i], st + offA[i]);
            LDSM4(f.alo[i], st + (uint32_t)kRegB + offA[i]);
        }
#pragma unroll
        for (int jp = 0; jp < 4; jp++) {
            LDSM4(f.bhi[jp], st + 2u * kRegB + offB[jp]);
            LDSM4(f.blo[jp], st + 3u * kRegB + offB[jp]);
        }
    };

    float acc[2][8][4];
#pragma unroll
    for (int i = 0; i < 2; i++)
#pragma unroll
        for (int j = 0; j < 8; j++)
#pragma unroll
            for (int q = 0; q < 4; q++) acc[i][j][q] = 0.f;

    auto mmaAll = [&](const Frags& f) {
#pragma unroll
        for (int i = 0; i < 2; i++)
#pragma unroll
            for (int j = 0; j < 8; j++) {
                int jp = j >> 1, s2 = (j & 1) * 2;
                mma16816(acc[i][j], f.ahi[i], &f.bhi[jp][s2]);
                mma16816(acc[i][j], f.ahi[i], &f.blo[jp][s2]);
                mma16816(acc[i][j], f.alo[i], &f.bhi[jp][s2]);
            }
    };

    Frags fA, fB;
    int offCur = 0, offNext = kStageB, offThird = 2 * kStageB;

    // prologue: fill stages 0 and 1, stage staging regs with block 2
    loadBlk(0);
    storeBlk(offCur);
    loadBlk(1);
    storeBlk(offNext);
    if (KB > 2) loadBlk(2);
    __syncthreads();
    ldsmFrags(fA, offCur);

    auto body = [&](int kb, Frags& cur, Frags& nxt) {
        if (kb + 2 < KB) storeBlk(offThird);   // staging holds block kb+2
        if (kb + 3 < KB) loadBlk(kb + 3);      // refill staging (distance 3)
        if (kb + 1 < KB) ldsmFrags(nxt, offNext);  // prefetch next frags (stage full)
        mmaAll(cur);
        __syncthreads();
        int t = offCur; offCur = offNext; offNext = offThird; offThird = t;
    };

    for (int kb = 0; kb < KB; kb += 2) {
        body(kb,     fA, fB);
        body(kb + 1, fB, fA);
    }

    // ---------------- epilogue ----------------
    const int realEnd = g_poff[e] + g_cnt[e];
    const float* biasE = bias + (size_t)e * ND + (size_t)bx * kBN;
    const int r0 = wm * 32 + (lane >> 2);
    const int c0 = (lane & 3) * 2;

#pragma unroll
    for (int i = 0; i < 2; i++)
#pragma unroll
        for (int hh = 0; hh < 2; hh++) {
            int r = row0 + r0 + i * 16 + hh * 8;
            if (r >= realEnd) continue;
            if (!SECOND) {
                uint32_t* hrh = g_h + (size_t)r * (kH / 2) + (size_t)bx * (kBN / 2);
                uint32_t* hrl = hrh + kHPlane;
#pragma unroll
                for (int j = 0; j < 8; j++) {
                    int col = wn * 64 + j * 8 + c0;
                    float v0 = geluf(acc[i][j][hh * 2 + 0] + biasE[col]);
                    float v1 = geluf(acc[i][j][hh * 2 + 1] + biasE[col + 1]);
                    uint32_t hp, lp;
                    split_pack(v0, v1, hp, lp);
                    hrh[col >> 1] = hp;
                    hrl[col >> 1] = lp;
                }
            } else {
                int n = g_perm[r];
                float sc = g_prob[n];
                float* orow = OutP + (size_t)n * kC + (size_t)bx * kBN;
#pragma unroll
                for (int j = 0; j < 8; j++) {
                    int col = wn * 64 + j * 8 + c0;
                    float2 v;
                    v.x = (acc[i][j][hh * 2 + 0] + biasE[col]) * sc;
                    v.y = (acc[i][j][hh * 2 + 1] + biasE[col + 1]) * sc;
                    *(float2*)(orow + col) = v;
                }
            }
        }
}

// ---------------- launch ----------------
extern "C" void kernel_launch(void* const* d_in, const int* in_sizes, int n_in,
                              void* d_out, int out_size) {
    const float* x  = (const float*)d_in[0];
    const float* Wr = (const float*)d_in[1];
    const float* br = (const float*)d_in[2];
    const float* W1 = (const float*)d_in[3];
    const float* b1 = (const float*)d_in[4];
    const float* W2 = (const float*)d_in[5];
    const float* b2 = (const float*)d_in[6];
    float* out = (float*)d_out;
    (void)n_in;

    reset_kernel<<<1, 32>>>();
    router_kernel<<<kN / 8, 256>>>(x, Wr, br);
    float* auxp = (out_size > kN * kC) ? out + (size_t)kN * kC : nullptr;
    offsets_kernel<<<1, 1>>>(auxp);
    gather_kernel<<<kN / 8, 256>>>(x);

    moe_mma<false><<<dim3(kH / kBN, kNRT), 256, kDynSmem>>>(W1, b1, nullptr);
    moe_mma<true ><<<dim3(kC / kBN, kNRT), 256, kDynSmem>>>(W2, b2, out);
}

// round 15
// speedup vs baseline: 1.4113x; 1.0026x over previous
#include <cuda_runtime.h>
#include <cuda_bf16.h>
#include <cstdint>
#include <cstddef>

// ---------------- problem constants ----------------
constexpr int kC  = 1024;
constexpr int kE  = 8;
constexpr int kH  = 4096;
constexpr int kN  = 8192;
constexpr int kBM = 128;               // CTA M tile
constexpr int kBN = 128;               // CTA N tile
constexpr int kRMax = kN + kE * kBM;   // 9216 padded rows
constexpr int kNRT  = kRMax / kBM;     // 72 row tiles

// --- R7 fallback layout (48B row stride, k16 stages) ---
constexpr int kRegB48  = kBM * 48;        // 6144 B
constexpr int kStage48 = 4 * kRegB48;     // 24576 B
constexpr int kDyn48   = 2 * kStage48;    // 49152 B (no opt-in)

// --- k32 primary layout (tight 32B row stride, k16 sub-blocks) ---
constexpr int kRegB32  = kBM * 32;        // 4096 B per region
constexpr int kSubB    = 4 * kRegB32;     // 16384 B per k16 sub-block
constexpr int kStage32 = 2 * kSubB;       // 32768 B per k32 stage
constexpr int kDyn64   = 2 * kStage32;    // 65536 B (needs opt-in)

// ---------------- device scratch (189MB profile, proven safe) ----------------
__device__ float g_xg[(size_t)kRMax * kC];        // gathered tokens fp32
__device__ float g_h [(size_t)kRMax * kH];        // hidden activations fp32
__device__ float g_prob[kN];
__device__ int   g_idx[kN];
__device__ int   g_perm[kRMax];
__device__ int   g_cnt[kE];
__device__ int   g_cur[kE];
__device__ int   g_poff[kE + 1];

// ---------------- helpers ----------------
__device__ __forceinline__ uint32_t smem_u32(const void* p) {
    uint32_t a;
    asm("{ .reg .u64 t; cvta.to.shared.u64 t, %1; cvt.u32.u64 %0, t; }" : "=r"(a) : "l"(p));
    return a;
}

#define LDSM4(r, a) \
    asm volatile("ldmatrix.sync.aligned.m8n8.x4.shared.b16 {%0,%1,%2,%3}, [%4];" \
                 : "=r"((r)[0]), "=r"((r)[1]), "=r"((r)[2]), "=r"((r)[3]) : "r"(a))

__device__ __forceinline__ void mma16816(float* c, const uint32_t* a, const uint32_t* b) {
    asm volatile(
        "mma.sync.aligned.m16n8k16.row.col.f32.bf16.bf16.f32 "
        "{%0,%1,%2,%3}, {%4,%5,%6,%7}, {%8,%9}, {%0,%1,%2,%3};\n"
        : "+f"(c[0]), "+f"(c[1]), "+f"(c[2]), "+f"(c[3])
        : "r"(a[0]), "r"(a[1]), "r"(a[2]), "r"(a[3]), "r"(b[0]), "r"(b[1]));
}

__device__ __forceinline__ float geluf(float v) {
    return 0.5f * v * (1.0f + erff(v * 0.70710678118654752f));
}
// pack {v1,v0} -> bf16x2 (v0 low), RN rounding (bit-identical to __float2bfloat16)
__device__ __forceinline__ uint32_t cvt_bf16x2(float v0, float v1) {
    uint32_t r;
    asm("cvt.rn.bf16x2.f32 %0, %1, %2;" : "=r"(r) : "f"(v1), "f"(v0));
    return r;
}
__device__ __forceinline__ void split_pack(float v0, float v1, uint32_t& hp, uint32_t& lp) {
    hp = cvt_bf16x2(v0, v1);
    float h0 = __uint_as_float(hp << 16);
    float h1 = __uint_as_float(hp & 0xFFFF0000u);
    lp = cvt_bf16x2(v0 - h0, v1 - h1);
}

// ---------------- small kernels (proven) ----------------
__global__ void reset_kernel() {
    int t = threadIdx.x;
    if (t < kE) { g_cnt[t] = 0; g_cur[t] = 0; }
}

__global__ void router_kernel(const float* __restrict__ x,
                              const float* __restrict__ Wr,
                              const float* __restrict__ br) {
    int tok  = (blockIdx.x * blockDim.x + threadIdx.x) >> 5;
    int lane = threadIdx.x & 31;
    if (tok >= kN) return;
    const float* xr = x + (size_t)tok * kC;
    float acc[kE];
#pragma unroll
    for (int e = 0; e < kE; e++) acc[e] = 0.f;
    for (int c = lane; c < kC; c += 32) {
        float xv = xr[c];
        const float4* w = (const float4*)(Wr + (size_t)c * kE);
        float4 w0 = w[0], w1 = w[1];
        acc[0] += xv * w0.x; acc[1] += xv * w0.y; acc[2] += xv * w0.z; acc[3] += xv * w0.w;
        acc[4] += xv * w1.x; acc[5] += xv * w1.y; acc[6] += xv * w1.z; acc[7] += xv * w1.w;
    }
#pragma unroll
    for (int e = 0; e < kE; e++)
        for (int o = 16; o > 0; o >>= 1)
            acc[e] += __shfl_xor_sync(0xffffffffu, acc[e], o);
    if (lane == 0) {
        float m = -1e30f; int bi = 0;
#pragma unroll
        for (int e = 0; e < kE; e++) {
            acc[e] += br[e];
            if (acc[e] > m) { m = acc[e]; bi = e; }
        }
        float s = 0.f;
#pragma unroll
        for (int e = 0; e < kE; e++) s += expf(acc[e] - m);
        g_prob[tok] = 1.f / s;
        g_idx[tok]  = bi;
        atomicAdd(&g_cnt[bi], 1);
    }
}

__global__ void offsets_kernel(float* aux_out) {
    if (threadIdx.x == 0) {
        int p = 0; float s = 0.f;
#pragma unroll
        for (int e = 0; e < kE; e++) {
            g_poff[e] = p;
            int c = g_cnt[e];
            p += (c + kBM - 1) / kBM * kBM;
            float f = (float)c / (float)kN;
            float d = f - (1.0f / (float)kE);
            s += d * d;
        }
        g_poff[kE] = p;
        if (aux_out) *aux_out = s / (float)kE;
    }
}

__global__ void gather_kernel(const float* __restrict__ x) {
    int tok  = (blockIdx.x * blockDim.x + threadIdx.x) >> 5;
    int lane = threadIdx.x & 31;
    if (tok >= kN) return;
    int e = g_idx[tok];
    int pos = 0;
    if (lane == 0) pos = g_poff[e] + atomicAdd(&g_cur[e], 1);
    pos = __shfl_sync(0xffffffffu, pos, 0);
    if (lane == 0) g_perm[pos] = tok;
    const float4* src = (const float4*)(x + (size_t)tok * kC);
    float4* dst = (float4*)(g_xg + (size_t)pos * kC);
#pragma unroll
    for (int i = lane; i < kC / 4; i += 32) dst[i] = src[i];
}

// ---------------- shared epilogue ----------------
template <bool SECOND>
__device__ __forceinline__ void epilogue(
    float acc[2][8][4], const float* biasE, float* OutP,
    int row0, int realEnd, int bx, int wm, int wn, int lane) {
    constexpr int ND = SECOND ? kC : kH;
    (void)ND;
    const int r0 = wm * 32 + (lane >> 2);
    const int c0 = (lane & 3) * 2;
#pragma unroll
    for (int i = 0; i < 2; i++)
#pragma unroll
        for (int hh = 0; hh < 2; hh++) {
            int r = row0 + r0 + i * 16 + hh * 8;
            if (r >= realEnd) continue;
            if (!SECOND) {
                float* drow = g_h + (size_t)r * kH + (size_t)bx * kBN;
#pragma unroll
                for (int j = 0; j < 8; j++) {
                    int col = wn * 64 + j * 8 + c0;
                    float2 v;
                    v.x = geluf(acc[i][j][hh * 2 + 0] + biasE[col]);
                    v.y = geluf(acc[i][j][hh * 2 + 1] + biasE[col + 1]);
                    *(float2*)(drow + col) = v;
                }
            } else {
                int n = g_perm[r];
                float sc = g_prob[n];
                float* orow = OutP + (size_t)n * kC + (size_t)bx * kBN;
#pragma unroll
                for (int j = 0; j < 8; j++) {
                    int col = wn * 64 + j * 8 + c0;
                    float2 v;
                    v.x = (acc[i][j][hh * 2 + 0] + biasE[col]) * sc;
                    v.y = (acc[i][j][hh * 2 + 1] + biasE[col + 1]) * sc;
                    *(float2*)(orow + col) = v;
                }
            }
        }
}

// ---------------- PRIMARY: k32 blocks, 2x32KB stages (needs 64KB opt-in) ----
struct Frags {
    uint32_t ahi[2][4], alo[2][4], bhi[4][4], blo[4][4];
};

template <bool SECOND>
__global__ __launch_bounds__(256)
void moe_mma32(const float* __restrict__ Wsrc, const float* __restrict__ bias,
               float* __restrict__ OutP) {
    constexpr int KDIM = SECOND ? kH : kC;
    constexpr int ND   = SECOND ? kC : kH;
    constexpr int KB32 = KDIM / 32;          // 32 : 128

    extern __shared__ char smc[];
    const uint32_t sb = smem_u32(smc);

    const int rt = blockIdx.y, bx = blockIdx.x;
    const int row0 = rt * kBM;
    if (row0 >= g_poff[kE]) return;
    int e = 0;
    while (e < kE - 1 && row0 >= g_poff[e + 1]) e++;

    const float* A = (SECOND ? g_h : g_xg) + (size_t)row0 * KDIM;
    const float* B = Wsrc + (size_t)e * KDIM * ND + (size_t)bx * kBN;

    const int tid  = threadIdx.x;
    const int warp = tid >> 5;
    const int lane = tid & 31;
    const int wm   = warp & 3;
    const int wn   = warp >> 2;

    // A fill: thread -> (row = tid>>1, k-octet = tid&1); fp32 source
    const int arow = tid >> 1, ah = tid & 1;
    const float* Aload = A + (size_t)arow * KDIM + ah * 8;
    // B fill: thread -> (n = tid>>1, k-octet = tid&1); fp32 source
    const int bn = tid >> 1, bkp = tid & 1;
    const float* Bload = B + (size_t)bkp * 8 * ND + bn;

    float ra[16], rb[16];
    auto loadBlk32 = [&](int kb) {
#pragma unroll
        for (int s2 = 0; s2 < 2; s2++) {
            const float* ap = Aload + (kb * 32 + s2 * 16);
            float4 a0 = *(const float4*)(ap);
            float4 a1 = *(const float4*)(ap + 4);
            ra[s2*8+0]=a0.x; ra[s2*8+1]=a0.y; ra[s2*8+2]=a0.z; ra[s2*8+3]=a0.w;
            ra[s2*8+4]=a1.x; ra[s2*8+5]=a1.y; ra[s2*8+6]=a1.z; ra[s2*8+7]=a1.w;
#pragma unroll
            for (int i = 0; i < 8; i++)
                rb[s2*8+i] = Bload[(size_t)(kb * 32 + s2 * 16 + i) * ND];
        }
    };
    auto storeBlk32 = [&](int stageOff) {
#pragma unroll
        for (int s2 = 0; s2 < 2; s2++) {
            char* base = smc + stageOff + s2 * kSubB + (size_t)tid * 16;
            uint32_t h[4], l[4];
#pragma unroll
            for (int i = 0; i < 4; i++) split_pack(ra[s2*8+2*i], ra[s2*8+2*i+1], h[i], l[i]);
            *(uint4*)(base)           = make_uint4(h[0], h[1], h[2], h[3]);
            *(uint4*)(base + kRegB32) = make_uint4(l[0], l[1], l[2], l[3]);
#pragma unroll
            for (int i = 0; i < 4; i++) split_pack(rb[s2*8+2*i], rb[s2*8+2*i+1], h[i], l[i]);
            *(uint4*)(base + 2 * kRegB32) = make_uint4(h[0], h[1], h[2], h[3]);
            *(uint4*)(base + 3 * kRegB32) = make_uint4(l[0], l[1], l[2], l[3]);
        }
    };

    // frag offsets within one k16 sub-block (tight 32B stride; R13-proven)
    uint32_t offA[2], offB[4];
#pragma unroll
    for (int i = 0; i < 2; i++) {
        uint32_t row = wm * 32 + i * 16 + ((lane >> 3) & 1) * 8 + (lane & 7);
        offA[i] = row * 32 + (lane >> 4) * 16;
    }
#pragma unroll
    for (int jp = 0; jp < 4; jp++) {
        uint32_t row = wn * 64 + jp * 16 + (lane >> 4) * 8 + (lane & 7);
        offB[jp] = row * 32 + ((lane >> 3) & 1) * 16;
    }

    auto ldsmFrags = [&](Frags& f, uint32_t subBase) {
        const uint32_t st = sb + subBase;
#pragma unroll
        for (int i = 0; i < 2; i++) {
            LDSM4(f.ahi[i], st + offA[i]);
            LDSM4(f.alo[i], st + (uint32_t)kRegB32 + offA[i]);
        }
#pragma unroll
        for (int jp = 0; jp < 4; jp++) {
            LDSM4(f.bhi[jp], st + 2u * kRegB32 + offB[jp]);
            LDSM4(f.blo[jp], st + 3u * kRegB32 + offB[jp]);
        }
    };

    float acc[2][8][4];
#pragma unroll
    for (int i = 0; i < 2; i++)
#pragma unroll
        for (int j = 0; j < 8; j++)
#pragma unroll
            for (int q = 0; q < 4; q++) acc[i][j][q] = 0.f;

    auto mmaAll = [&](const Frags& f) {
#pragma unroll
        for (int i = 0; i < 2; i++)
#pragma unroll
            for (int j = 0; j < 8; j++) {
                int jp = j >> 1, s2 = (j & 1) * 2;
                mma16816(acc[i][j], f.ahi[i], &f.bhi[jp][s2]);
                mma16816(acc[i][j], f.ahi[i], &f.blo[jp][s2]);
                mma16816(acc[i][j], f.alo[i], &f.bhi[jp][s2]);
            }
    };

    Frags fA, fB;
    loadBlk32(0);
    storeBlk32(0);
    __syncthreads();

    for (int kb = 0; kb < KB32; kb++) {
        const int s = kb & 1;
        const uint32_t off = (uint32_t)s * kStage32;

        ldsmFrags(fA, off);              // sub0 frags
        ldsmFrags(fB, off + kSubB);      // sub1 frags (latency hides under fA MMAs)
        if (kb + 1 < KB32) loadBlk32(kb + 1);   // LDG next block, covered by MMAs
        mmaAll(fA);
        mmaAll(fB);
        if (kb + 1 < KB32) storeBlk32(off ^ (uint32_t)kStage32);
        __syncthreads();
    }

    const int realEnd = g_poff[e] + g_cnt[e];
    const float* biasE = bias + (size_t)e * ND + (size_t)bx * kBN;
    epilogue<SECOND>(acc, biasE, OutP, row0, realEnd, bx, wm, wn, lane);
}

// ---------------- FALLBACK: R7 verbatim (48KB, k16 double-buffer) -----------
template <bool SECOND>
__global__ __launch_bounds__(256)
void moe_mma16(const float* __restrict__ Wsrc, const float* __restrict__ bias,
               float* __restrict__ OutP) {
    constexpr int KDIM = SECOND ? kH : kC;
    constexpr int ND   = SECOND ? kC : kH;
    constexpr int KB   = KDIM / 16;

    extern __shared__ char smc[];
    const uint32_t sb = smem_u32(smc);

    const int rt = blockIdx.y, bx = blockIdx.x;
    const int row0 = rt * kBM;
    if (row0 >= g_poff[kE]) return;
    int e = 0;
    while (e < kE - 1 && row0 >= g_poff[e + 1]) e++;

    const float* A = (SECOND ? g_h : g_xg) + (size_t)row0 * KDIM;
    const float* B = Wsrc + (size_t)e * KDIM * ND + (size_t)bx * kBN;

    const int tid  = threadIdx.x;
    const int warp = tid >> 5;
    const int lane = tid & 31;
    const int wm   = warp & 3;
    const int wn   = warp >> 2;

    const int arow = tid >> 1, ah = tid & 1;
    const float* Aload = A + (size_t)arow * KDIM + ah * 8;
    const int bn = tid & 127, bkp = tid >> 7;
    const float* Bload = B + (size_t)bkp * 8 * ND + bn;

    float ra[8], rb[8], ra2[8], rb2[8];
    auto load_regs = [&](int kb, float* a, float* b) {
        float4 a0 = *(const float4*)(Aload + kb * 16);
        float4 a1 = *(const float4*)(Aload + kb * 16 + 4);
        a[0]=a0.x; a[1]=a0.y; a[2]=a0.z; a[3]=a0.w;
        a[4]=a1.x; a[5]=a1.y; a[6]=a1.z; a[7]=a1.w;
#pragma unroll
        for (int i = 0; i < 8; i++)
            b[i] = Bload[(size_t)(kb * 16 + i) * ND];
    };
    auto store_stage = [&](int s, const float* a, const float* b) {
        char* base = smc + (size_t)s * kStage48;
        uint32_t h[4], l[4];
#pragma unroll
        for (int i = 0; i < 4; i++) split_pack(a[2*i], a[2*i+1], h[i], l[i]);
        *(uint4*)(base + (size_t)arow * 48 + ah * 16) = make_uint4(h[0], h[1], h[2], h[3]);
        *(uint4*)(base + kRegB48 + (size_t)arow * 48 + ah * 16) = make_uint4(l[0], l[1], l[2], l[3]);
#pragma unroll
        for (int i = 0; i < 4; i++) {
            uint32_t hp, lp;
            split_pack(b[2*i], b[2*i+1], hp, lp);
            *(uint32_t*)(base + 2*kRegB48 + (size_t)bn * 48 + bkp * 16 + i * 4) = hp;
            *(uint32_t*)(base + 3*kRegB48 + (size_t)bn * 48 + bkp * 16 + i * 4) = lp;
        }
    };

    uint32_t offA[2], offB[4];
#pragma unroll
    for (int i = 0; i < 2; i++) {
        uint32_t row = wm * 32 + i * 16 + ((lane >> 3) & 1) * 8 + (lane & 7);
        offA[i] = row * 48 + (lane >> 4) * 16;
    }
#pragma unroll
    for (int jp = 0; jp < 4; jp++) {
        uint32_t row = wn * 64 + jp * 16 + (lane >> 4) * 8 + (lane & 7);
        offB[jp] = row * 48 + ((lane >> 3) & 1) * 16;
    }

    float acc[2][8][4];
#pragma unroll
    for (int i = 0; i < 2; i++)
#pragma unroll
        for (int j = 0; j < 8; j++)
#pragma unroll
            for (int q = 0; q < 4; q++) acc[i][j][q] = 0.f;

    load_regs(0, ra, rb);
    store_stage(0, ra, rb);
    __syncthreads();
    load_regs(1, ra, rb);

    for (int kb = 0; kb < KB; kb++) {
        const int s = kb & 1;
        if (kb + 1 < KB) store_stage(s ^ 1, ra, rb);
        if (kb + 2 < KB) load_regs(kb + 2, ra2, rb2);

        const uint32_t st = sb + (uint32_t)s * kStage48;
        uint32_t ahi[2][4], alo[2][4], bhi[4][4], blo[4][4];
#pragma unroll
        for (int i = 0; i < 2; i++) {
            LDSM4(ahi[i], st + offA[i]);
            LDSM4(alo[i], st + (uint32_t)kRegB48 + offA[i]);
        }
#pragma unroll
        for (int jp = 0; jp < 4; jp++) {
            LDSM4(bhi[jp], st + 2u * kRegB48 + offB[jp]);
            LDSM4(blo[jp], st + 3u * kRegB48 + offB[jp]);
        }
#pragma unroll
        for (int i = 0; i < 2; i++)
#pragma unroll
            for (int j = 0; j < 8; j++) {
                int jp = j >> 1, s2 = (j & 1) * 2;
                mma16816(acc[i][j], ahi[i], &bhi[jp][s2]);
                mma16816(acc[i][j], ahi[i], &blo[jp][s2]);
                mma16816(acc[i][j], alo[i], &bhi[jp][s2]);
            }
#pragma unroll
        for (int q = 0; q < 8; q++) { ra[q] = ra2[q]; rb[q] = rb2[q]; }
        __syncthreads();
    }

    const int realEnd = g_poff[e] + g_cnt[e];
    const float* biasE = bias + (size_t)e * ND + (size_t)bx * kBN;
    epilogue<SECOND>(acc, biasE, OutP, row0, realEnd, bx, wm, wn, lane);
}

// ---------------- launch ----------------
extern "C" void kernel_launch(void* const* d_in, const int* in_sizes, int n_in,
                              void* d_out, int out_size) {
    const float* x  = (const float*)d_in[0];
    const float* Wr = (const float*)d_in[1];
    const float* br = (const float*)d_in[2];
    const float* W1 = (const float*)d_in[3];
    const float* b1 = (const float*)d_in[4];
    const float* W2 = (const float*)d_in[5];
    const float* b2 = (const float*)d_in[6];
    float* out = (float*)d_out;
    (void)n_in;

    reset_kernel<<<1, 32>>>();
    router_kernel<<<kN / 8, 256>>>(x, Wr, br);
    float* auxp = (out_size > kN * kC) ? out + (size_t)kN * kC : nullptr;
    offsets_kernel<<<1, 1>>>(auxp);
    gather_kernel<<<kN / 8, 256>>>(x);

    // Probe: opt-in 64KB dynamic smem. If either call fails, fall back to the
    // proven 48KB kernel. (Deterministic per environment; re-evaluated each call.)
    cudaError_t r1 = cudaFuncSetAttribute(
        moe_mma32<false>, cudaFuncAttributeMaxDynamicSharedMemorySize, kDyn64);
    cudaError_t r2 = cudaFuncSetAttribute(
        moe_mma32<true>, cudaFuncAttributeMaxDynamicSharedMemorySize, kDyn64);
    if (r1 == cudaSuccess && r2 == cudaSuccess) {
        moe_mma32<false><<<dim3(kH / kBN, kNRT), 256, kDyn64>>>(W1, b1, nullptr);
        moe_mma32<true ><<<dim3(kC / kBN, kNRT), 256, kDyn64>>>(W2, b2, out);
    } else {
        cudaGetLastError();   // clear sticky error from the failed attribute set
        moe_mma16<false><<<dim3(kH / kBN, kNRT), 256, kDyn48>>>(W1, b1, nullptr);
        moe_mma16<true ><<<dim3(kC / kBN, kNRT), 256, kDyn48>>>(W2, b2, out);
    }
}

// round 16
// speedup vs baseline: 1.5477x; 1.0966x over previous
#include <cuda_runtime.h>
#include <cuda_bf16.h>
#include <cstdint>
#include <cstddef>

// ---------------- problem constants ----------------
constexpr int kC  = 1024;
constexpr int kE  = 8;
constexpr int kH  = 4096;
constexpr int kN  = 8192;
constexpr int kBM = 64;                // CTA M tile (half-height)
constexpr int kBN = 128;               // CTA N tile
constexpr int kPad = 128;              // expert padding granularity (rows)
constexpr int kRMax = kN + kE * kPad;  // 9216 padded rows
constexpr int kNRT  = kRMax / kBM;     // 144 row tiles of 64
// smem regions (48B row stride, proven conflict-free)
constexpr int kRegA   = kBM * 48;      // 3072 B per A plane (64 rows)
constexpr int kRegBsz = kBN * 48;      // 6144 B per B plane (128 n)
constexpr int kStageB = 2 * kRegA + 2 * kRegBsz;   // 18432 B
constexpr int kDynSmem = 2 * kStageB;  // 36864 B (< 48KB, no opt-in)

// ---------------- device scratch (189MB profile, proven safe) ----------------
__device__ float g_xg[(size_t)kRMax * kC];        // gathered tokens fp32
__device__ float g_h [(size_t)kRMax * kH];        // hidden activations fp32
__device__ float g_prob[kN];
__device__ int   g_idx[kN];
__device__ int   g_perm[kRMax];
__device__ int   g_cnt[kE];
__device__ int   g_cur[kE];
__device__ int   g_poff[kE + 1];

// ---------------- helpers ----------------
__device__ __forceinline__ uint32_t smem_u32(const void* p) {
    uint32_t a;
    asm("{ .reg .u64 t; cvta.to.shared.u64 t, %1; cvt.u32.u64 %0, t; }" : "=r"(a) : "l"(p));
    return a;
}

#define LDSM4(r, a) \
    asm volatile("ldmatrix.sync.aligned.m8n8.x4.shared.b16 {%0,%1,%2,%3}, [%4];" \
                 : "=r"((r)[0]), "=r"((r)[1]), "=r"((r)[2]), "=r"((r)[3]) : "r"(a))

__device__ __forceinline__ void mma16816(float* c, const uint32_t* a, const uint32_t* b) {
    asm volatile(
        "mma.sync.aligned.m16n8k16.row.col.f32.bf16.bf16.f32 "
        "{%0,%1,%2,%3}, {%4,%5,%6,%7}, {%8,%9}, {%0,%1,%2,%3};\n"
        : "+f"(c[0]), "+f"(c[1]), "+f"(c[2]), "+f"(c[3])
        : "r"(a[0]), "r"(a[1]), "r"(a[2]), "r"(a[3]), "r"(b[0]), "r"(b[1]));
}

__device__ __forceinline__ float geluf(float v) {
    return 0.5f * v * (1.0f + erff(v * 0.70710678118654752f));
}
// pack {v1,v0} -> bf16x2 (v0 low), RN rounding (bit-identical to __float2bfloat16)
__device__ __forceinline__ uint32_t cvt_bf16x2(float v0, float v1) {
    uint32_t r;
    asm("cvt.rn.bf16x2.f32 %0, %1, %2;" : "=r"(r) : "f"(v1), "f"(v0));
    return r;
}
__device__ __forceinline__ void split_pack(float v0, float v1, uint32_t& hp, uint32_t& lp) {
    hp = cvt_bf16x2(v0, v1);
    float h0 = __uint_as_float(hp << 16);
    float h1 = __uint_as_float(hp & 0xFFFF0000u);
    lp = cvt_bf16x2(v0 - h0, v1 - h1);
}

// ---------------- small kernels (proven) ----------------
__global__ void reset_kernel() {
    int t = threadIdx.x;
    if (t < kE) { g_cnt[t] = 0; g_cur[t] = 0; }
}

__global__ void router_kernel(const float* __restrict__ x,
                              const float* __restrict__ Wr,
                              const float* __restrict__ br) {
    int tok  = (blockIdx.x * blockDim.x + threadIdx.x) >> 5;
    int lane = threadIdx.x & 31;
    if (tok >= kN) return;
    const float* xr = x + (size_t)tok * kC;
    float acc[kE];
#pragma unroll
    for (int e = 0; e < kE; e++) acc[e] = 0.f;
    for (int c = lane; c < kC; c += 32) {
        float xv = xr[c];
        const float4* w = (const float4*)(Wr + (size_t)c * kE);
        float4 w0 = w[0], w1 = w[1];
        acc[0] += xv * w0.x; acc[1] += xv * w0.y; acc[2] += xv * w0.z; acc[3] += xv * w0.w;
        acc[4] += xv * w1.x; acc[5] += xv * w1.y; acc[6] += xv * w1.z; acc[7] += xv * w1.w;
    }
#pragma unroll
    for (int e = 0; e < kE; e++)
        for (int o = 16; o > 0; o >>= 1)
            acc[e] += __shfl_xor_sync(0xffffffffu, acc[e], o);
    if (lane == 0) {
        float m = -1e30f; int bi = 0;
#pragma unroll
        for (int e = 0; e < kE; e++) {
            acc[e] += br[e];
            if (acc[e] > m) { m = acc[e]; bi = e; }
        }
        float s = 0.f;
#pragma unroll
        for (int e = 0; e < kE; e++) s += expf(acc[e] - m);
        g_prob[tok] = 1.f / s;
        g_idx[tok]  = bi;
        atomicAdd(&g_cnt[bi], 1);
    }
}

__global__ void offsets_kernel(float* aux_out) {
    if (threadIdx.x == 0) {
        int p = 0; float s = 0.f;
#pragma unroll
        for (int e = 0; e < kE; e++) {
            g_poff[e] = p;
            int c = g_cnt[e];
            p += (c + kPad - 1) / kPad * kPad;     // pad to 128 (64-tiles never straddle)
            float f = (float)c / (float)kN;
            float d = f - (1.0f / (float)kE);
            s += d * d;
        }
        g_poff[kE] = p;
        if (aux_out) *aux_out = s / (float)kE;
    }
}

__global__ void gather_kernel(const float* __restrict__ x) {
    int tok  = (blockIdx.x * blockDim.x + threadIdx.x) >> 5;
    int lane = threadIdx.x & 31;
    if (tok >= kN) return;
    int e = g_idx[tok];
    int pos = 0;
    if (lane == 0) pos = g_poff[e] + atomicAdd(&g_cur[e], 1);
    pos = __shfl_sync(0xffffffffu, pos, 0);
    if (lane == 0) g_perm[pos] = tok;
    const float4* src = (const float4*)(x + (size_t)tok * kC);
    float4* dst = (float4*)(g_xg + (size_t)pos * kC);
#pragma unroll
    for (int i = lane; i < kC / 4; i += 32) dst[i] = src[i];
}

// ---------------- grouped GEMM: 128-thread CTAs, 64x128 tile, co-resident ----
// SECOND=false: g_h = gelu(g_xg @ W1[e] + b1)
// SECOND=true : out[perm[r]] = prob * (g_h @ W2[e] + b2)
template <bool SECOND>
__global__ __launch_bounds__(128)
void moe_mma(const float* __restrict__ Wsrc, const float* __restrict__ bias,
             float* __restrict__ OutP) {
    constexpr int KDIM = SECOND ? kH : kC;
    constexpr int ND   = SECOND ? kC : kH;
    constexpr int KB   = KDIM / 16;

    extern __shared__ char smc[];
    const uint32_t sb = smem_u32(smc);

    const int rt = blockIdx.y, bx = blockIdx.x;
    const int row0 = rt * kBM;
    if (row0 >= g_poff[kE]) return;
    int e = 0;
    while (e < kE - 1 && row0 >= g_poff[e + 1]) e++;

    const float* A = (SECOND ? g_h : g_xg) + (size_t)row0 * KDIM;
    const float* B = Wsrc + (size_t)e * KDIM * ND + (size_t)bx * kBN;

    const int tid  = threadIdx.x;
    const int warp = tid >> 5;
    const int lane = tid & 31;
    const int wm   = warp & 1;      // 2 row-blocks of 32
    const int wn   = warp >> 1;     // 2 col-blocks of 64

    // A fill: thread -> (row = tid>>1 of 64, k-octet = tid&1)
    const int arow = tid >> 1, ah = tid & 1;
    const float* Aload = A + (size_t)arow * KDIM + ah * 8;
    // B fill: thread -> n col = tid (both k-octets)
    const int bn = tid;
    const float* Bload = B + bn;

    float ra[8], rb[16];
    auto loadBlk = [&](int kb) {
        float4 a0 = *(const float4*)(Aload + kb * 16);
        float4 a1 = *(const float4*)(Aload + kb * 16 + 4);
        ra[0]=a0.x; ra[1]=a0.y; ra[2]=a0.z; ra[3]=a0.w;
        ra[4]=a1.x; ra[5]=a1.y; ra[6]=a1.z; ra[7]=a1.w;
#pragma unroll
        for (int i = 0; i < 16; i++)
            rb[i] = Bload[(size_t)(kb * 16 + i) * ND];
    };
    auto storeBlk = [&](int s) {
        char* base = smc + (size_t)s * kStageB;
        uint32_t h[4], l[4];
#pragma unroll
        for (int i = 0; i < 4; i++) split_pack(ra[2*i], ra[2*i+1], h[i], l[i]);
        *(uint4*)(base + (size_t)arow * 48 + ah * 16)         = make_uint4(h[0], h[1], h[2], h[3]);
        *(uint4*)(base + kRegA + (size_t)arow * 48 + ah * 16) = make_uint4(l[0], l[1], l[2], l[3]);
        char* bb = base + 2 * kRegA + (size_t)bn * 48;
#pragma unroll
        for (int oc = 0; oc < 2; oc++) {
#pragma unroll
            for (int i = 0; i < 4; i++)
                split_pack(rb[oc*8+2*i], rb[oc*8+2*i+1], h[i], l[i]);
            *(uint4*)(bb + oc * 16)           = make_uint4(h[0], h[1], h[2], h[3]);
            *(uint4*)(bb + kRegBsz + oc * 16) = make_uint4(l[0], l[1], l[2], l[3]);
        }
    };

    // ldmatrix byte offsets (row stride 48B)
    uint32_t offA[2], offB[4];
#pragma unroll
    for (int i = 0; i < 2; i++) {
        uint32_t row = wm * 32 + i * 16 + ((lane >> 3) & 1) * 8 + (lane & 7);
        offA[i] = row * 48 + (lane >> 4) * 16;
    }
#pragma unroll
    for (int jp = 0; jp < 4; jp++) {
        uint32_t row = wn * 64 + jp * 16 + (lane >> 4) * 8 + (lane & 7);
        offB[jp] = row * 48 + ((lane >> 3) & 1) * 16;
    }

    float acc[2][8][4];
#pragma unroll
    for (int i = 0; i < 2; i++)
#pragma unroll
        for (int j = 0; j < 8; j++)
#pragma unroll
            for (int q = 0; q < 4; q++) acc[i][j][q] = 0.f;

    loadBlk(0);
    storeBlk(0);
    __syncthreads();

    for (int kb = 0; kb < KB; kb++) {
        const int s = kb & 1;
        const uint32_t st = sb + (uint32_t)s * kStageB;

        uint32_t ahi[2][4], alo[2][4], bhi[4][4], blo[4][4];
#pragma unroll
        for (int i = 0; i < 2; i++) {
            LDSM4(ahi[i], st + offA[i]);
            LDSM4(alo[i], st + (uint32_t)kRegA + offA[i]);
        }
#pragma unroll
        for (int jp = 0; jp < 4; jp++) {
            LDSM4(bhi[jp], st + 2u * kRegA + offB[jp]);
            LDSM4(blo[jp], st + 2u * kRegA + (uint32_t)kRegBsz + offB[jp]);
        }

        if (kb + 1 < KB) loadBlk(kb + 1);   // LDG next block; hidden under MMAs

#pragma unroll
        for (int i = 0; i < 2; i++)
#pragma unroll
            for (int j = 0; j < 8; j++) {
                int jp = j >> 1, s2 = (j & 1) * 2;
                mma16816(acc[i][j], ahi[i], &bhi[jp][s2]);
                mma16816(acc[i][j], ahi[i], &blo[jp][s2]);
                mma16816(acc[i][j], alo[i], &bhi[jp][s2]);
            }

        if (kb + 1 < KB) storeBlk(s ^ 1);
        __syncthreads();
    }

    // ---------------- epilogue ----------------
    const int realEnd = g_poff[e] + g_cnt[e];
    const float* biasE = bias + (size_t)e * ND + (size_t)bx * kBN;
    const int r0 = wm * 32 + (lane >> 2);
    const int c0 = (lane & 3) * 2;

#pragma unroll
    for (int i = 0; i < 2; i++)
#pragma unroll
        for (int hh = 0; hh < 2; hh++) {
            int r = row0 + r0 + i * 16 + hh * 8;
            if (r >= realEnd) continue;
            if (!SECOND) {
                float* drow = g_h + (size_t)r * kH + (size_t)bx * kBN;
#pragma unroll
                for (int j = 0; j < 8; j++) {
                    int col = wn * 64 + j * 8 + c0;
                    float2 v;
                    v.x = geluf(acc[i][j][hh * 2 + 0] + biasE[col]);
                    v.y = geluf(acc[i][j][hh * 2 + 1] + biasE[col + 1]);
                    *(float2*)(drow + col) = v;
                }
            } else {
                int n = g_perm[r];
                float sc = g_prob[n];
                float* orow = OutP + (size_t)n * kC + (size_t)bx * kBN;
#pragma unroll
                for (int j = 0; j < 8; j++) {
                    int col = wn * 64 + j * 8 + c0;
                    float2 v;
                    v.x = (acc[i][j][hh * 2 + 0] + biasE[col]) * sc;
                    v.y = (acc[i][j][hh * 2 + 1] + biasE[col + 1]) * sc;
                    *(float2*)(orow + col) = v;
                }
            }
        }
}

// ---------------- launch ----------------
extern "C" void kernel_launch(void* const* d_in, const int* in_sizes, int n_in,
                              void* d_out, int out_size) {
    const float* x  = (const float*)d_in[0];
    const float* Wr = (const float*)d_in[1];
    const float* br = (const float*)d_in[2];
    const float* W1 = (const float*)d_in[3];
    const float* b1 = (const float*)d_in[4];
    const float* W2 = (const float*)d_in[5];
    const float* b2 = (const float*)d_in[6];
    float* out = (float*)d_out;
    (void)n_in;

    reset_kernel<<<1, 32>>>();
    router_kernel<<<kN / 8, 256>>>(x, Wr, br);
    float* auxp = (out_size > kN * kC) ? out + (size_t)kN * kC : nullptr;
    offsets_kernel<<<1, 1>>>(auxp);
    gather_kernel<<<kN / 8, 256>>>(x);

    moe_mma<false><<<dim3(kH / kBN, kNRT), 128, kDynSmem>>>(W1, b1, nullptr);
    moe_mma<true ><<<dim3(kC / kBN, kNRT), 128, kDynSmem>>>(W2, b2, out);
}

// round 17
// speedup vs baseline: 1.8157x; 1.1732x over previous
#include <cuda_runtime.h>
#include <cuda_bf16.h>
#include <cstdint>
#include <cstddef>

// ---------------- problem constants ----------------
constexpr int kC  = 1024;
constexpr int kE  = 8;
constexpr int kH  = 4096;
constexpr int kN  = 8192;
constexpr int kBM = 128;               // CTA M tile
constexpr int kBN = 128;               // CTA N tile
constexpr int kRMax = kN + kE * kBM;   // 9216 padded rows
constexpr int kNRT  = kRMax / kBM;     // 72 row tiles
constexpr int kRegB  = kBM * 48;       // 6144 B per region (128 rows x 48B stride)
constexpr int kStageB = 4 * kRegB;     // Ahi|Alo|Bhi|Blo = 24576 B
constexpr int kDynSmem = 2 * kStageB;  // 49152 B = 48KB (no opt-in needed)

// ---------------- device scratch (189MB profile, proven safe) ----------------
__device__ float g_xg[(size_t)kRMax * kC];        // gathered tokens fp32
__device__ float g_h [(size_t)kRMax * kH];        // hidden activations fp32
__device__ float g_prob[kN];
__device__ int   g_idx[kN];
__device__ int   g_perm[kRMax];
__device__ int   g_cnt[kE];
__device__ int   g_cur[kE];
__device__ int   g_poff[kE + 1];

// ---------------- helpers ----------------
__device__ __forceinline__ uint32_t smem_u32(const void* p) {
    uint32_t a;
    asm("{ .reg .u64 t; cvta.to.shared.u64 t, %1; cvt.u32.u64 %0, t; }" : "=r"(a) : "l"(p));
    return a;
}

#define LDSM4(r, a) \
    asm volatile("ldmatrix.sync.aligned.m8n8.x4.shared.b16 {%0,%1,%2,%3}, [%4];" \
                 : "=r"((r)[0]), "=r"((r)[1]), "=r"((r)[2]), "=r"((r)[3]) : "r"(a))

// NOTE: non-volatile — pure register op, lets ptxas schedule/interleave freely.
__device__ __forceinline__ void mma16816(float* c, const uint32_t* a, const uint32_t* b) {
    asm("mma.sync.aligned.m16n8k16.row.col.f32.bf16.bf16.f32 "
        "{%0,%1,%2,%3}, {%4,%5,%6,%7}, {%8,%9}, {%0,%1,%2,%3};\n"
        : "+f"(c[0]), "+f"(c[1]), "+f"(c[2]), "+f"(c[3])
        : "r"(a[0]), "r"(a[1]), "r"(a[2]), "r"(a[3]), "r"(b[0]), "r"(b[1]));
}

__device__ __forceinline__ float geluf(float v) {
    return 0.5f * v * (1.0f + erff(v * 0.70710678118654752f));
}
// pack {v1,v0} -> bf16x2 (v0 low), RN rounding (bit-identical to __float2bfloat16)
__device__ __forceinline__ uint32_t cvt_bf16x2(float v0, float v1) {
    uint32_t r;
    asm("cvt.rn.bf16x2.f32 %0, %1, %2;" : "=r"(r) : "f"(v1), "f"(v0));
    return r;
}
__device__ __forceinline__ void split_pack(float v0, float v1, uint32_t& hp, uint32_t& lp) {
    hp = cvt_bf16x2(v0, v1);
    float h0 = __uint_as_float(hp << 16);
    float h1 = __uint_as_float(hp & 0xFFFF0000u);
    lp = cvt_bf16x2(v0 - h0, v1 - h1);
}

// ---------------- small kernels (proven) ----------------
__global__ void reset_kernel() {
    int t = threadIdx.x;
    if (t < kE) { g_cnt[t] = 0; g_cur[t] = 0; }
}

__global__ void router_kernel(const float* __restrict__ x,
                              const float* __restrict__ Wr,
                              const float* __restrict__ br) {
    int tok  = (blockIdx.x * blockDim.x + threadIdx.x) >> 5;
    int lane = threadIdx.x & 31;
    if (tok >= kN) return;
    const float* xr = x + (size_t)tok * kC;
    float acc[kE];
#pragma unroll
    for (int e = 0; e < kE; e++) acc[e] = 0.f;
    for (int c = lane; c < kC; c += 32) {
        float xv = xr[c];
        const float4* w = (const float4*)(Wr + (size_t)c * kE);
        float4 w0 = w[0], w1 = w[1];
        acc[0] += xv * w0.x; acc[1] += xv * w0.y; acc[2] += xv * w0.z; acc[3] += xv * w0.w;
        acc[4] += xv * w1.x; acc[5] += xv * w1.y; acc[6] += xv * w1.z; acc[7] += xv * w1.w;
    }
#pragma unroll
    for (int e = 0; e < kE; e++)
        for (int o = 16; o > 0; o >>= 1)
            acc[e] += __shfl_xor_sync(0xffffffffu, acc[e], o);
    if (lane == 0) {
        float m = -1e30f; int bi = 0;
#pragma unroll
        for (int e = 0; e < kE; e++) {
            acc[e] += br[e];
            if (acc[e] > m) { m = acc[e]; bi = e; }
        }
        float s = 0.f;
#pragma unroll
        for (int e = 0; e < kE; e++) s += expf(acc[e] - m);
        g_prob[tok] = 1.f / s;
        g_idx[tok]  = bi;
        atomicAdd(&g_cnt[bi], 1);
    }
}

__global__ void offsets_kernel(float* aux_out) {
    if (threadIdx.x == 0) {
        int p = 0; float s = 0.f;
#pragma unroll
        for (int e = 0; e < kE; e++) {
            g_poff[e] = p;
            int c = g_cnt[e];
            p += (c + kBM - 1) / kBM * kBM;
            float f = (float)c / (float)kN;
            float d = f - (1.0f / (float)kE);
            s += d * d;
        }
        g_poff[kE] = p;
        if (aux_out) *aux_out = s / (float)kE;
    }
}

__global__ void gather_kernel(const float* __restrict__ x) {
    int tok  = (blockIdx.x * blockDim.x + threadIdx.x) >> 5;
    int lane = threadIdx.x & 31;
    if (tok >= kN) return;
    int e = g_idx[tok];
    int pos = 0;
    if (lane == 0) pos = g_poff[e] + atomicAdd(&g_cur[e], 1);
    pos = __shfl_sync(0xffffffffu, pos, 0);
    if (lane == 0) g_perm[pos] = tok;
    const float4* src = (const float4*)(x + (size_t)tok * kC);
    float4* dst = (float4*)(g_xg + (size_t)pos * kC);
#pragma unroll
    for (int i = lane; i < kC / 4; i += 32) dst[i] = src[i];
}

// ---------------- grouped GEMM (R7 structure, term-major MMA order) ---------
// SECOND=false: g_h = gelu(g_xg @ W1[e] + b1)
// SECOND=true : out[perm[r]] = prob * (g_h @ W2[e] + b2)
template <bool SECOND>
__global__ __launch_bounds__(256)
void moe_mma(const float* __restrict__ Wsrc, const float* __restrict__ bias,
             float* __restrict__ OutP) {
    constexpr int KDIM = SECOND ? kH : kC;
    constexpr int ND   = SECOND ? kC : kH;
    constexpr int KB   = KDIM / 16;

    extern __shared__ char smc[];
    const uint32_t sb = smem_u32(smc);

    const int rt = blockIdx.y, bx = blockIdx.x;
    const int row0 = rt * kBM;
    if (row0 >= g_poff[kE]) return;
    int e = 0;
    while (e < kE - 1 && row0 >= g_poff[e + 1]) e++;

    const float* A = (SECOND ? g_h : g_xg) + (size_t)row0 * KDIM;
    const float* B = Wsrc + (size_t)e * KDIM * ND + (size_t)bx * kBN;

    const int tid  = threadIdx.x;
    const int warp = tid >> 5;
    const int lane = tid & 31;
    const int wm   = warp & 3;
    const int wn   = warp >> 2;

    const int arow = tid >> 1, ah = tid & 1;
    const float* Aload = A + (size_t)arow * KDIM + ah * 8;
    const int bn = tid & 127, bkp = tid >> 7;
    const float* Bload = B + (size_t)bkp * 8 * ND + bn;

    float ra[8], rb[8], ra2[8], rb2[8];
    auto load_regs = [&](int kb, float* a, float* b) {
        float4 a0 = *(const float4*)(Aload + kb * 16);
        float4 a1 = *(const float4*)(Aload + kb * 16 + 4);
        a[0]=a0.x; a[1]=a0.y; a[2]=a0.z; a[3]=a0.w;
        a[4]=a1.x; a[5]=a1.y; a[6]=a1.z; a[7]=a1.w;
#pragma unroll
        for (int i = 0; i < 8; i++)
            b[i] = Bload[(size_t)(kb * 16 + i) * ND];
    };
    auto store_stage = [&](int s, const float* a, const float* b) {
        char* base = smc + (size_t)s * kStageB;
        uint32_t h[4], l[4];
#pragma unroll
        for (int i = 0; i < 4; i++) split_pack(a[2*i], a[2*i+1], h[i], l[i]);
        *(uint4*)(base + (size_t)arow * 48 + ah * 16) = make_uint4(h[0], h[1], h[2], h[3]);
        *(uint4*)(base + kRegB + (size_t)arow * 48 + ah * 16) = make_uint4(l[0], l[1], l[2], l[3]);
#pragma unroll
        for (int i = 0; i < 4; i++) {
            uint32_t hp, lp;
            split_pack(b[2*i], b[2*i+1], hp, lp);
            *(uint32_t*)(base + 2*kRegB + (size_t)bn * 48 + bkp * 16 + i * 4) = hp;
            *(uint32_t*)(base + 3*kRegB + (size_t)bn * 48 + bkp * 16 + i * 4) = lp;
        }
    };

    uint32_t offA[2], offB[4];
#pragma unroll
    for (int i = 0; i < 2; i++) {
        uint32_t row = wm * 32 + i * 16 + ((lane >> 3) & 1) * 8 + (lane & 7);
        offA[i] = row * 48 + (lane >> 4) * 16;
    }
#pragma unroll
    for (int jp = 0; jp < 4; jp++) {
        uint32_t row = wn * 64 + jp * 16 + (lane >> 4) * 8 + (lane & 7);
        offB[jp] = row * 48 + ((lane >> 3) & 1) * 16;
    }

    float acc[2][8][4];
#pragma unroll
    for (int i = 0; i < 2; i++)
#pragma unroll
        for (int j = 0; j < 8; j++)
#pragma unroll
            for (int q = 0; q < 4; q++) acc[i][j][q] = 0.f;

    load_regs(0, ra, rb);
    store_stage(0, ra, rb);
    __syncthreads();
    load_regs(1, ra, rb);

    for (int kb = 0; kb < KB; kb++) {
        const int s = kb & 1;
        if (kb + 1 < KB) store_stage(s ^ 1, ra, rb);
        if (kb + 2 < KB) load_regs(kb + 2, ra2, rb2);

        const uint32_t st = sb + (uint32_t)s * kStageB;
        uint32_t ahi[2][4], alo[2][4], bhi[4][4], blo[4][4];
#pragma unroll
        for (int i = 0; i < 2; i++) {
            LDSM4(ahi[i], st + offA[i]);
            LDSM4(alo[i], st + (uint32_t)kRegB + offA[i]);
        }
#pragma unroll
        for (int jp = 0; jp < 4; jp++) {
            LDSM4(bhi[jp], st + 2u * kRegB + offB[jp]);
            LDSM4(blo[jp], st + 3u * kRegB + offB[jp]);
        }

        // term-major ordering: 16 independent MMAs per term -> no RAW chains
#pragma unroll
        for (int i = 0; i < 2; i++)
#pragma unroll
            for (int j = 0; j < 8; j++)
                mma16816(acc[i][j], ahi[i], &bhi[j >> 1][(j & 1) * 2]);
#pragma unroll
        for (int i = 0; i < 2; i++)
#pragma unroll
            for (int j = 0; j < 8; j++)
                mma16816(acc[i][j], ahi[i], &blo[j >> 1][(j & 1) * 2]);
#pragma unroll
        for (int i = 0; i < 2; i++)
#pragma unroll
            for (int j = 0; j < 8; j++)
                mma16816(acc[i][j], alo[i], &bhi[j >> 1][(j & 1) * 2]);

#pragma unroll
        for (int q = 0; q < 8; q++) { ra[q] = ra2[q]; rb[q] = rb2[q]; }
        __syncthreads();
    }

    // ---------------- epilogue ----------------
    const int realEnd = g_poff[e] + g_cnt[e];
    const float* biasE = bias + (size_t)e * ND + (size_t)bx * kBN;
    const int r0 = wm * 32 + (lane >> 2);
    const int c0 = (lane & 3) * 2;

#pragma unroll
    for (int i = 0; i < 2; i++)
#pragma unroll
        for (int hh = 0; hh < 2; hh++) {
            int r = row0 + r0 + i * 16 + hh * 8;
            if (r >= realEnd) continue;
            if (!SECOND) {
                float* drow = g_h + (size_t)r * kH + (size_t)bx * kBN;
#pragma unroll
                for (int j = 0; j < 8; j++) {
                    int col = wn * 64 + j * 8 + c0;
                    float2 v;
                    v.x = geluf(acc[i][j][hh * 2 + 0] + biasE[col]);
                    v.y = geluf(acc[i][j][hh * 2 + 1] + biasE[col + 1]);
                    *(float2*)(drow + col) = v;
                }
            } else {
                int n = g_perm[r];
                float sc = g_prob[n];
                float* orow = OutP + (size_t)n * kC + (size_t)bx * kBN;
#pragma unroll
                for (int j = 0; j < 8; j++) {
                    int col = wn * 64 + j * 8 + c0;
                    float2 v;
                    v.x = (acc[i][j][hh * 2 + 0] + biasE[col]) * sc;
                    v.y = (acc[i][j][hh * 2 + 1] + biasE[col + 1]) * sc;
                    *(float2*)(orow + col) = v;
                }
            }
        }
}

// ---------------- launch ----------------
extern "C" void kernel_launch(void* const* d_in, const int* in_sizes, int n_in,
                              void* d_out, int out_size) {
    const float* x  = (const float*)d_in[0];
    const float* Wr = (const float*)d_in[1];
    const float* br = (const float*)d_in[2];
    const float* W1 = (const float*)d_in[3];
    const float* b1 = (const float*)d_in[4];
    const float* W2 = (const float*)d_in[5];
    const float* b2 = (const float*)d_in[6];
    float* out = (float*)d_out;
    (void)n_in;

    reset_kernel<<<1, 32>>>();
    router_kernel<<<kN / 8, 256>>>(x, Wr, br);
    float* auxp = (out_size > kN * kC) ? out + (size_t)kN * kC : nullptr;
    offsets_kernel<<<1, 1>>>(auxp);
    gather_kernel<<<kN / 8, 256>>>(x);

    moe_mma<false><<<dim3(kH / kBN, kNRT), 256, kDynSmem>>>(W1, b1, nullptr);
    moe_mma<true ><<<dim3(kC / kBN, kNRT), 256, kDynSmem>>>(W2, b2, out);
}